// round 4
// baseline (speedup 1.0000x reference)
#include <cuda_runtime.h>
#include <cstdint>

#define N_NODES 50000
#define N_EDGES 640000
#define D 128
#define OUT 128

// Scratch (no allocs allowed): h = feat@Wp.T, and ordered-key max accumulator.
__device__ float    g_h[(size_t)N_NODES * D];
__device__ unsigned g_neigh[(size_t)N_NODES * D];

// Order-preserving float -> uint key (monotone): max over keys == max over floats.
__device__ __forceinline__ unsigned fkey(float f) {
    unsigned u = __float_as_uint(f);
    return (u & 0x80000000u) ? ~u : (u | 0x80000000u);
}
// Inverse. Key 0 is below every real key -> node with no incoming edges -> 0.0f
// (matches reference's deg==0 masking).
__device__ __forceinline__ float fdec(unsigned u) {
    if (u == 0u) return 0.0f;
    return (u & 0x80000000u) ? __uint_as_float(u ^ 0x80000000u) : __uint_as_float(~u);
}

// ---------------------------------------------------------------------------
// GEMM1: g_h[n][o] = sum_k feat[n][k] * Wp[o][k] + bp[o]
// Block tile: 64 rows x 128 outs, K-chunks of 32. 256 threads, 4x8 register tile.
// ---------------------------------------------------------------------------
#define BM 64
#define PAD 33

__global__ __launch_bounds__(256) void gemm_pool(
    const float* __restrict__ feat, const float* __restrict__ Wp,
    const float* __restrict__ bp, int nrows)
{
    __shared__ float Fs[BM][PAD];
    __shared__ float Ws[128][PAD];

    const int tid = threadIdx.x;
    const int tx = tid & 15;        // out groups: o = tx + 16*j, j<8
    const int ty = tid >> 4;        // row groups: n = ty*4 + i, i<4
    const int row0 = blockIdx.x * BM;

    float acc[4][8];
#pragma unroll
    for (int i = 0; i < 4; i++)
#pragma unroll
        for (int j = 0; j < 8; j++) acc[i][j] = 0.0f;

    for (int c = 0; c < 4; c++) {
        // Load feat tile: 64 x 32 floats (512 float4)
#pragma unroll
        for (int v = tid; v < 512; v += 256) {
            int n = v >> 3, k4 = v & 7;
            int row = row0 + n;
            float4 val = make_float4(0.f, 0.f, 0.f, 0.f);
            if (row < nrows)
                val = *reinterpret_cast<const float4*>(&feat[(size_t)row * D + c * 32 + k4 * 4]);
            Fs[n][k4 * 4 + 0] = val.x; Fs[n][k4 * 4 + 1] = val.y;
            Fs[n][k4 * 4 + 2] = val.z; Fs[n][k4 * 4 + 3] = val.w;
        }
        // Load W tile: 128 x 32 floats (1024 float4)
#pragma unroll
        for (int v = tid; v < 1024; v += 256) {
            int o = v >> 3, k4 = v & 7;
            float4 val = *reinterpret_cast<const float4*>(&Wp[(size_t)o * D + c * 32 + k4 * 4]);
            Ws[o][k4 * 4 + 0] = val.x; Ws[o][k4 * 4 + 1] = val.y;
            Ws[o][k4 * 4 + 2] = val.z; Ws[o][k4 * 4 + 3] = val.w;
        }
        __syncthreads();

#pragma unroll
        for (int kk = 0; kk < 32; kk++) {
            float f[4], w[8];
#pragma unroll
            for (int i = 0; i < 4; i++) f[i] = Fs[ty * 4 + i][kk];
#pragma unroll
            for (int j = 0; j < 8; j++) w[j] = Ws[tx + 16 * j][kk];
#pragma unroll
            for (int i = 0; i < 4; i++)
#pragma unroll
                for (int j = 0; j < 8; j++) acc[i][j] += f[i] * w[j];
        }
        __syncthreads();
    }

#pragma unroll
    for (int i = 0; i < 4; i++) {
        int row = row0 + ty * 4 + i;
        if (row >= nrows) continue;
#pragma unroll
        for (int j = 0; j < 8; j++) {
            int o = tx + 16 * j;
            g_h[(size_t)row * D + o] = acc[i][j] + bp[o];
        }
    }
}

// ---------------------------------------------------------------------------
// Edge scatter-max: m = h[src]*w ; atomicMax(key) into g_neigh[dst].
// 8 edges per 256-thread block; 32 lanes * float4 cover D=128.
// Indices are int32 (JAX x64 disabled downgrades int64 -> int32).
// ---------------------------------------------------------------------------
__global__ __launch_bounds__(256) void edge_kernel(
    const float* __restrict__ weight,
    const int* __restrict__ src, const int* __restrict__ dst,
    int nedges)
{
    int e = blockIdx.x * 8 + (threadIdx.x >> 5);
    if (e >= nedges) return;
    int lane = threadIdx.x & 31;

    int s = src[e];
    int d = dst[e];
    if ((unsigned)s >= N_NODES || (unsigned)d >= N_NODES) return;  // defensive
    float w = weight[e];

    float4 v = *reinterpret_cast<const float4*>(&g_h[(size_t)s * D + lane * 4]);
    unsigned* out = &g_neigh[(size_t)d * D + lane * 4];
    atomicMax(out + 0, fkey(v.x * w));
    atomicMax(out + 1, fkey(v.y * w));
    atomicMax(out + 2, fkey(v.z * w));
    atomicMax(out + 3, fkey(v.w * w));
}

// ---------------------------------------------------------------------------
// GEMM2: out[n][o] = sum_{k<128} feat[n][k]*Wn[o][k]
//                  + sum_{k<128} fdec(g_neigh[n][k])*Wn[o][128+k] + bn[o]
// Same tiling; 8 K-chunks of 32 (first 4 from feat, last 4 from decoded neigh).
// ---------------------------------------------------------------------------
__global__ __launch_bounds__(256) void gemm_out(
    const float* __restrict__ feat, const float* __restrict__ Wn,
    const float* __restrict__ bn, float* __restrict__ out, int nrows)
{
    __shared__ float Fs[BM][PAD];
    __shared__ float Ws[128][PAD];

    const int tid = threadIdx.x;
    const int tx = tid & 15;
    const int ty = tid >> 4;
    const int row0 = blockIdx.x * BM;

    float acc[4][8];
#pragma unroll
    for (int i = 0; i < 4; i++)
#pragma unroll
        for (int j = 0; j < 8; j++) acc[i][j] = 0.0f;

    for (int c = 0; c < 8; c++) {
        // Load source tile: feat for c<4, decoded neigh for c>=4
#pragma unroll
        for (int v = tid; v < 512; v += 256) {
            int n = v >> 3, k4 = v & 7;
            int row = row0 + n;
            float4 val = make_float4(0.f, 0.f, 0.f, 0.f);
            if (row < nrows) {
                if (c < 4) {
                    val = *reinterpret_cast<const float4*>(&feat[(size_t)row * D + c * 32 + k4 * 4]);
                } else {
                    uint4 u = *reinterpret_cast<const uint4*>(&g_neigh[(size_t)row * D + (c - 4) * 32 + k4 * 4]);
                    val = make_float4(fdec(u.x), fdec(u.y), fdec(u.z), fdec(u.w));
                }
            }
            Fs[n][k4 * 4 + 0] = val.x; Fs[n][k4 * 4 + 1] = val.y;
            Fs[n][k4 * 4 + 2] = val.z; Fs[n][k4 * 4 + 3] = val.w;
        }
        // Load W tile: Wn has row stride 256
#pragma unroll
        for (int v = tid; v < 1024; v += 256) {
            int o = v >> 3, k4 = v & 7;
            float4 val = *reinterpret_cast<const float4*>(&Wn[(size_t)o * 256 + c * 32 + k4 * 4]);
            Ws[o][k4 * 4 + 0] = val.x; Ws[o][k4 * 4 + 1] = val.y;
            Ws[o][k4 * 4 + 2] = val.z; Ws[o][k4 * 4 + 3] = val.w;
        }
        __syncthreads();

#pragma unroll
        for (int kk = 0; kk < 32; kk++) {
            float f[4], w[8];
#pragma unroll
            for (int i = 0; i < 4; i++) f[i] = Fs[ty * 4 + i][kk];
#pragma unroll
            for (int j = 0; j < 8; j++) w[j] = Ws[tx + 16 * j][kk];
#pragma unroll
            for (int i = 0; i < 4; i++)
#pragma unroll
                for (int j = 0; j < 8; j++) acc[i][j] += f[i] * w[j];
        }
        __syncthreads();
    }

#pragma unroll
    for (int i = 0; i < 4; i++) {
        int row = row0 + ty * 4 + i;
        if (row >= nrows) continue;
#pragma unroll
        for (int j = 0; j < 8; j++) {
            int o = tx + 16 * j;
            out[(size_t)row * OUT + o] = acc[i][j] + bn[o];
        }
    }
}

extern "C" void kernel_launch(void* const* d_in, const int* in_sizes, int n_in,
                              void* d_out, int out_size)
{
    const float* feat   = (const float*)d_in[0];
    const float* weight = (const float*)d_in[1];
    const int*   src    = (const int*)d_in[2];
    const int*   dst    = (const int*)d_in[3];
    const float* Wp     = (const float*)d_in[4];
    const float* bp     = (const float*)d_in[5];
    const float* Wn     = (const float*)d_in[6];
    const float* bn     = (const float*)d_in[7];
    float* out = (float*)d_out;

    void* neigh_ptr = nullptr;
    cudaGetSymbolAddress(&neigh_ptr, g_neigh);
    cudaMemsetAsync(neigh_ptr, 0, sizeof(unsigned) * (size_t)N_NODES * D);

    int grid_rows = (N_NODES + BM - 1) / BM;   // 782
    gemm_pool<<<grid_rows, 256>>>(feat, Wp, bp, N_NODES);

    int edge_blocks = (N_EDGES + 7) / 8;       // 80000
    edge_kernel<<<edge_blocks, 256>>>(weight, src, dst, N_EDGES);

    gemm_out<<<grid_rows, 256>>>(feat, Wn, bn, out, N_NODES);
}

// round 5
// speedup vs baseline: 1.1618x; 1.1618x over previous
#include <cuda_runtime.h>
#include <cstdint>
#include <math_constants.h>

#define N_NODES 50000
#define N_EDGES 640000
#define D 128
#define OUT 128

// Scratch (no allocs allowed)
__device__ float g_h[(size_t)N_NODES * D];       // feat @ Wp.T
__device__ float g_neighf[(size_t)N_NODES * D];  // segment-max result
__device__ int   g_deg[N_NODES];
__device__ int   g_off[N_NODES];
__device__ int   g_cursor[N_NODES];
__device__ int2  g_csr[N_EDGES];                 // packed {src, weight-bits}

// ---------------------------------------------------------------------------
// GEMM1: g_h[n][o] = sum_k feat[n][k] * Wp[o][k] + bp[o]
// ---------------------------------------------------------------------------
#define BM 64
#define PAD 33

__global__ __launch_bounds__(256) void gemm_pool(
    const float* __restrict__ feat, const float* __restrict__ Wp,
    const float* __restrict__ bp, int nrows)
{
    __shared__ float Fs[BM][PAD];
    __shared__ float Ws[128][PAD];

    const int tid = threadIdx.x;
    const int tx = tid & 15;
    const int ty = tid >> 4;
    const int row0 = blockIdx.x * BM;

    float acc[4][8];
#pragma unroll
    for (int i = 0; i < 4; i++)
#pragma unroll
        for (int j = 0; j < 8; j++) acc[i][j] = 0.0f;

    for (int c = 0; c < 4; c++) {
#pragma unroll
        for (int v = tid; v < 512; v += 256) {
            int n = v >> 3, k4 = v & 7;
            int row = row0 + n;
            float4 val = make_float4(0.f, 0.f, 0.f, 0.f);
            if (row < nrows)
                val = *reinterpret_cast<const float4*>(&feat[(size_t)row * D + c * 32 + k4 * 4]);
            Fs[n][k4 * 4 + 0] = val.x; Fs[n][k4 * 4 + 1] = val.y;
            Fs[n][k4 * 4 + 2] = val.z; Fs[n][k4 * 4 + 3] = val.w;
        }
#pragma unroll
        for (int v = tid; v < 1024; v += 256) {
            int o = v >> 3, k4 = v & 7;
            float4 val = *reinterpret_cast<const float4*>(&Wp[(size_t)o * D + c * 32 + k4 * 4]);
            Ws[o][k4 * 4 + 0] = val.x; Ws[o][k4 * 4 + 1] = val.y;
            Ws[o][k4 * 4 + 2] = val.z; Ws[o][k4 * 4 + 3] = val.w;
        }
        __syncthreads();

#pragma unroll
        for (int kk = 0; kk < 32; kk++) {
            float f[4], w[8];
#pragma unroll
            for (int i = 0; i < 4; i++) f[i] = Fs[ty * 4 + i][kk];
#pragma unroll
            for (int j = 0; j < 8; j++) w[j] = Ws[tx + 16 * j][kk];
#pragma unroll
            for (int i = 0; i < 4; i++)
#pragma unroll
                for (int j = 0; j < 8; j++) acc[i][j] += f[i] * w[j];
        }
        __syncthreads();
    }

#pragma unroll
    for (int i = 0; i < 4; i++) {
        int row = row0 + ty * 4 + i;
        if (row >= nrows) continue;
#pragma unroll
        for (int j = 0; j < 8; j++) {
            int o = tx + 16 * j;
            g_h[(size_t)row * D + o] = acc[i][j] + bp[o];
        }
    }
}

// ---------------------------------------------------------------------------
// CSR build: histogram -> scan -> scatter
// ---------------------------------------------------------------------------
__global__ __launch_bounds__(256) void hist_kernel(const int* __restrict__ dst, int nedges)
{
    int e = blockIdx.x * 256 + threadIdx.x;
    if (e >= nedges) return;
    int d = dst[e];
    if ((unsigned)d < N_NODES) atomicAdd(&g_deg[d], 1);
}

// Single-block exclusive scan of g_deg -> g_off (and g_cursor copy).
__global__ __launch_bounds__(1024) void scan_kernel()
{
    __shared__ int totals[1024];
    const int CH = (N_NODES + 1023) / 1024;  // 49
    int t = threadIdx.x;
    int base = t * CH;

    int sum = 0;
    for (int i = 0; i < CH; i++) {
        int idx = base + i;
        if (idx < N_NODES) sum += g_deg[idx];
    }
    totals[t] = sum;
    __syncthreads();

    // in-place Hillis-Steele inclusive scan
    for (int s = 1; s < 1024; s <<= 1) {
        int v = (t >= s) ? totals[t - s] : 0;
        __syncthreads();
        totals[t] += v;
        __syncthreads();
    }

    int run = (t > 0) ? totals[t - 1] : 0;  // exclusive prefix
    for (int i = 0; i < CH; i++) {
        int idx = base + i;
        if (idx < N_NODES) {
            g_off[idx] = run;
            g_cursor[idx] = run;
            run += g_deg[idx];
        }
    }
}

__global__ __launch_bounds__(256) void scatter_kernel(
    const float* __restrict__ weight,
    const int* __restrict__ src, const int* __restrict__ dst, int nedges)
{
    int e = blockIdx.x * 256 + threadIdx.x;
    if (e >= nedges) return;
    int s = src[e];
    int d = dst[e];
    if ((unsigned)s >= N_NODES || (unsigned)d >= N_NODES) return;
    int pos = atomicAdd(&g_cursor[d], 1);
    g_csr[pos] = make_int2(s, __float_as_int(weight[e]));
}

// ---------------------------------------------------------------------------
// Aggregate: one warp per node; register max over incoming edges. No atomics.
// ---------------------------------------------------------------------------
__global__ __launch_bounds__(256) void aggregate_kernel()
{
    int n = blockIdx.x * 8 + (threadIdx.x >> 5);
    if (n >= N_NODES) return;
    int lane = threadIdx.x & 31;

    int off = g_off[n];
    int deg = g_deg[n];

    float4 acc = make_float4(-CUDART_INF_F, -CUDART_INF_F, -CUDART_INF_F, -CUDART_INF_F);
    for (int j = 0; j < deg; j++) {
        int2 e = g_csr[off + j];
        float w = __int_as_float(e.y);
        float4 v = *reinterpret_cast<const float4*>(&g_h[(size_t)e.x * D + lane * 4]);
        acc.x = fmaxf(acc.x, v.x * w);
        acc.y = fmaxf(acc.y, v.y * w);
        acc.z = fmaxf(acc.z, v.z * w);
        acc.w = fmaxf(acc.w, v.w * w);
    }
    if (deg == 0) acc = make_float4(0.f, 0.f, 0.f, 0.f);
    *reinterpret_cast<float4*>(&g_neighf[(size_t)n * D + lane * 4]) = acc;
}

// ---------------------------------------------------------------------------
// GEMM2: out = [feat | neigh] @ Wn.T + bn
// ---------------------------------------------------------------------------
__global__ __launch_bounds__(256) void gemm_out(
    const float* __restrict__ feat, const float* __restrict__ Wn,
    const float* __restrict__ bn, float* __restrict__ out, int nrows)
{
    __shared__ float Fs[BM][PAD];
    __shared__ float Ws[128][PAD];

    const int tid = threadIdx.x;
    const int tx = tid & 15;
    const int ty = tid >> 4;
    const int row0 = blockIdx.x * BM;

    float acc[4][8];
#pragma unroll
    for (int i = 0; i < 4; i++)
#pragma unroll
        for (int j = 0; j < 8; j++) acc[i][j] = 0.0f;

    for (int c = 0; c < 8; c++) {
#pragma unroll
        for (int v = tid; v < 512; v += 256) {
            int n = v >> 3, k4 = v & 7;
            int row = row0 + n;
            float4 val = make_float4(0.f, 0.f, 0.f, 0.f);
            if (row < nrows) {
                if (c < 4) {
                    val = *reinterpret_cast<const float4*>(&feat[(size_t)row * D + c * 32 + k4 * 4]);
                } else {
                    val = *reinterpret_cast<const float4*>(&g_neighf[(size_t)row * D + (c - 4) * 32 + k4 * 4]);
                }
            }
            Fs[n][k4 * 4 + 0] = val.x; Fs[n][k4 * 4 + 1] = val.y;
            Fs[n][k4 * 4 + 2] = val.z; Fs[n][k4 * 4 + 3] = val.w;
        }
#pragma unroll
        for (int v = tid; v < 1024; v += 256) {
            int o = v >> 3, k4 = v & 7;
            float4 val = *reinterpret_cast<const float4*>(&Wn[(size_t)o * 256 + c * 32 + k4 * 4]);
            Ws[o][k4 * 4 + 0] = val.x; Ws[o][k4 * 4 + 1] = val.y;
            Ws[o][k4 * 4 + 2] = val.z; Ws[o][k4 * 4 + 3] = val.w;
        }
        __syncthreads();

#pragma unroll
        for (int kk = 0; kk < 32; kk++) {
            float f[4], w[8];
#pragma unroll
            for (int i = 0; i < 4; i++) f[i] = Fs[ty * 4 + i][kk];
#pragma unroll
            for (int j = 0; j < 8; j++) w[j] = Ws[tx + 16 * j][kk];
#pragma unroll
            for (int i = 0; i < 4; i++)
#pragma unroll
                for (int j = 0; j < 8; j++) acc[i][j] += f[i] * w[j];
        }
        __syncthreads();
    }

#pragma unroll
    for (int i = 0; i < 4; i++) {
        int row = row0 + ty * 4 + i;
        if (row >= nrows) continue;
#pragma unroll
        for (int j = 0; j < 8; j++) {
            int o = tx + 16 * j;
            out[(size_t)row * OUT + o] = acc[i][j] + bn[o];
        }
    }
}

extern "C" void kernel_launch(void* const* d_in, const int* in_sizes, int n_in,
                              void* d_out, int out_size)
{
    const float* feat   = (const float*)d_in[0];
    const float* weight = (const float*)d_in[1];
    const int*   src    = (const int*)d_in[2];
    const int*   dst    = (const int*)d_in[3];
    const float* Wp     = (const float*)d_in[4];
    const float* bp     = (const float*)d_in[5];
    const float* Wn     = (const float*)d_in[6];
    const float* bn     = (const float*)d_in[7];
    float* out = (float*)d_out;

    void* deg_ptr = nullptr;
    cudaGetSymbolAddress(&deg_ptr, g_deg);
    cudaMemsetAsync(deg_ptr, 0, sizeof(int) * N_NODES);

    int grid_rows = (N_NODES + BM - 1) / BM;      // 782
    gemm_pool<<<grid_rows, 256>>>(feat, Wp, bp, N_NODES);

    int eb = (N_EDGES + 255) / 256;               // 2500
    hist_kernel<<<eb, 256>>>(dst, N_EDGES);
    scan_kernel<<<1, 1024>>>();
    scatter_kernel<<<eb, 256>>>(weight, src, dst, N_EDGES);

    aggregate_kernel<<<(N_NODES + 7) / 8, 256>>>();

    gemm_out<<<grid_rows, 256>>>(feat, Wn, bn, out, N_NODES);
}

// round 7
// speedup vs baseline: 1.2220x; 1.0519x over previous
#include <cuda_runtime.h>
#include <cstdint>
#include <math_constants.h>

#define N_NODES 50000
#define N_EDGES 640000
#define D 128
#define OUT 128

// Scratch (no allocs allowed)
__device__ float g_h[(size_t)N_NODES * D];       // feat @ Wp.T
__device__ float g_neighf[(size_t)N_NODES * D];  // segment-max result
__device__ int   g_deg[N_NODES];
__device__ int   g_off[N_NODES];
__device__ int   g_cursor[N_NODES];
__device__ int2  g_csr[N_EDGES];                 // packed {src, weight-bits}

// ---------------------------------------------------------------------------
// GEMM: 128x128 block tile, 256 threads, 8x8 micro-tile, k-major smem,
// 128-bit LDS. KC=16 K-chunk.  4 LDS.128 per 64 FFMA per thread.
// ---------------------------------------------------------------------------
#define KC 16
#define STRA 132   // padded k-major row stride in floats (16B aligned, bank-spread)

// GEMM1: g_h[n][o] = sum_k feat[n][k]*Wp[o][k] + bp[o]   (K = 128)
__global__ __launch_bounds__(256) void gemm_pool(
    const float* __restrict__ feat, const float* __restrict__ Wp,
    const float* __restrict__ bp, int nrows)
{
    __shared__ float As[KC][STRA];
    __shared__ float Bs[KC][STRA];

    const int tid = threadIdx.x;
    const int tx = tid & 15;        // col groups: tx*4 .. +3 and 64+tx*4 .. +3
    const int ty = tid >> 4;        // row group: ty*8 .. +7
    const int row0 = blockIdx.x * 128;

    float acc[8][8];
#pragma unroll
    for (int i = 0; i < 8; i++)
#pragma unroll
        for (int j = 0; j < 8; j++) acc[i][j] = 0.0f;

    for (int c = 0; c < 8; c++) {   // 8 chunks of KC=16 over K=128
        // A tile: 128 rows x 16 k = 512 float4; 2 per thread; store transposed
#pragma unroll
        for (int t = 0; t < 2; t++) {
            int idx = tid + t * 256;
            int row = idx >> 2, kq = idx & 3;
            float4 v = make_float4(0.f, 0.f, 0.f, 0.f);
            if (row0 + row < nrows)
                v = *reinterpret_cast<const float4*>(&feat[(size_t)(row0 + row) * D + c * KC + kq * 4]);
            As[kq * 4 + 0][row] = v.x; As[kq * 4 + 1][row] = v.y;
            As[kq * 4 + 2][row] = v.z; As[kq * 4 + 3][row] = v.w;
        }
        // B tile: 128 outs x 16 k
#pragma unroll
        for (int t = 0; t < 2; t++) {
            int idx = tid + t * 256;
            int o = idx >> 2, kq = idx & 3;
            float4 v = *reinterpret_cast<const float4*>(&Wp[(size_t)o * D + c * KC + kq * 4]);
            Bs[kq * 4 + 0][o] = v.x; Bs[kq * 4 + 1][o] = v.y;
            Bs[kq * 4 + 2][o] = v.z; Bs[kq * 4 + 3][o] = v.w;
        }
        __syncthreads();

#pragma unroll
        for (int kk = 0; kk < KC; kk++) {
            float4 a0 = *reinterpret_cast<const float4*>(&As[kk][ty * 8]);
            float4 a1 = *reinterpret_cast<const float4*>(&As[kk][ty * 8 + 4]);
            float4 b0 = *reinterpret_cast<const float4*>(&Bs[kk][tx * 4]);
            float4 b1 = *reinterpret_cast<const float4*>(&Bs[kk][64 + tx * 4]);
            float a[8] = {a0.x, a0.y, a0.z, a0.w, a1.x, a1.y, a1.z, a1.w};
            float b[8] = {b0.x, b0.y, b0.z, b0.w, b1.x, b1.y, b1.z, b1.w};
#pragma unroll
            for (int i = 0; i < 8; i++)
#pragma unroll
                for (int j = 0; j < 8; j++) acc[i][j] += a[i] * b[j];
        }
        __syncthreads();
    }

#pragma unroll
    for (int i = 0; i < 8; i++) {
        int row = row0 + ty * 8 + i;
        if (row >= nrows) continue;
        float4 r0, r1;
        r0.x = acc[i][0] + bp[tx * 4 + 0];  r0.y = acc[i][1] + bp[tx * 4 + 1];
        r0.z = acc[i][2] + bp[tx * 4 + 2];  r0.w = acc[i][3] + bp[tx * 4 + 3];
        r1.x = acc[i][4] + bp[64 + tx * 4 + 0]; r1.y = acc[i][5] + bp[64 + tx * 4 + 1];
        r1.z = acc[i][6] + bp[64 + tx * 4 + 2]; r1.w = acc[i][7] + bp[64 + tx * 4 + 3];
        *reinterpret_cast<float4*>(&g_h[(size_t)row * D + tx * 4]) = r0;
        *reinterpret_cast<float4*>(&g_h[(size_t)row * D + 64 + tx * 4]) = r1;
    }
}

// GEMM2: out[n][o] = sum_{k<256} cat(feat,neigh)[n][k]*Wn[o][k] + bn[o]
__global__ __launch_bounds__(256) void gemm_out(
    const float* __restrict__ feat, const float* __restrict__ Wn,
    const float* __restrict__ bn, float* __restrict__ out, int nrows)
{
    __shared__ float As[KC][STRA];
    __shared__ float Bs[KC][STRA];

    const int tid = threadIdx.x;
    const int tx = tid & 15;
    const int ty = tid >> 4;
    const int row0 = blockIdx.x * 128;

    float acc[8][8];
#pragma unroll
    for (int i = 0; i < 8; i++)
#pragma unroll
        for (int j = 0; j < 8; j++) acc[i][j] = 0.0f;

    for (int c = 0; c < 16; c++) {  // 16 chunks of 16 over K=256
        const float* Asrc = (c < 8) ? feat : g_neighf;
        int kbase = (c < 8) ? c * KC : (c - 8) * KC;
#pragma unroll
        for (int t = 0; t < 2; t++) {
            int idx = tid + t * 256;
            int row = idx >> 2, kq = idx & 3;
            float4 v = make_float4(0.f, 0.f, 0.f, 0.f);
            if (row0 + row < nrows)
                v = *reinterpret_cast<const float4*>(&Asrc[(size_t)(row0 + row) * D + kbase + kq * 4]);
            As[kq * 4 + 0][row] = v.x; As[kq * 4 + 1][row] = v.y;
            As[kq * 4 + 2][row] = v.z; As[kq * 4 + 3][row] = v.w;
        }
#pragma unroll
        for (int t = 0; t < 2; t++) {
            int idx = tid + t * 256;
            int o = idx >> 2, kq = idx & 3;
            float4 v = *reinterpret_cast<const float4*>(&Wn[(size_t)o * 256 + c * KC + kq * 4]);
            Bs[kq * 4 + 0][o] = v.x; Bs[kq * 4 + 1][o] = v.y;
            Bs[kq * 4 + 2][o] = v.z; Bs[kq * 4 + 3][o] = v.w;
        }
        __syncthreads();

#pragma unroll
        for (int kk = 0; kk < KC; kk++) {
            float4 a0 = *reinterpret_cast<const float4*>(&As[kk][ty * 8]);
            float4 a1 = *reinterpret_cast<const float4*>(&As[kk][ty * 8 + 4]);
            float4 b0 = *reinterpret_cast<const float4*>(&Bs[kk][tx * 4]);
            float4 b1 = *reinterpret_cast<const float4*>(&Bs[kk][64 + tx * 4]);
            float a[8] = {a0.x, a0.y, a0.z, a0.w, a1.x, a1.y, a1.z, a1.w};
            float b[8] = {b0.x, b0.y, b0.z, b0.w, b1.x, b1.y, b1.z, b1.w};
#pragma unroll
            for (int i = 0; i < 8; i++)
#pragma unroll
                for (int j = 0; j < 8; j++) acc[i][j] += a[i] * b[j];
        }
        __syncthreads();
    }

#pragma unroll
    for (int i = 0; i < 8; i++) {
        int row = row0 + ty * 8 + i;
        if (row >= nrows) continue;
        float4 r0, r1;
        r0.x = acc[i][0] + bn[tx * 4 + 0];  r0.y = acc[i][1] + bn[tx * 4 + 1];
        r0.z = acc[i][2] + bn[tx * 4 + 2];  r0.w = acc[i][3] + bn[tx * 4 + 3];
        r1.x = acc[i][4] + bn[64 + tx * 4 + 0]; r1.y = acc[i][5] + bn[64 + tx * 4 + 1];
        r1.z = acc[i][6] + bn[64 + tx * 4 + 2]; r1.w = acc[i][7] + bn[64 + tx * 4 + 3];
        *reinterpret_cast<float4*>(&out[(size_t)row * OUT + tx * 4]) = r0;
        *reinterpret_cast<float4*>(&out[(size_t)row * OUT + 64 + tx * 4]) = r1;
    }
}

// ---------------------------------------------------------------------------
// CSR build: histogram -> scan -> scatter
// ---------------------------------------------------------------------------
__global__ __launch_bounds__(256) void hist_kernel(const int* __restrict__ dst, int nedges)
{
    int e = blockIdx.x * 256 + threadIdx.x;
    if (e >= nedges) return;
    int d = dst[e];
    if ((unsigned)d < N_NODES) atomicAdd(&g_deg[d], 1);
}

__global__ __launch_bounds__(1024) void scan_kernel()
{
    __shared__ int totals[1024];
    const int CH = (N_NODES + 1023) / 1024;  // 49
    int t = threadIdx.x;
    int base = t * CH;

    int sum = 0;
#pragma unroll
    for (int i = 0; i < CH; i++) {
        int idx = base + i;
        if (idx < N_NODES) sum += g_deg[idx];
    }
    totals[t] = sum;
    __syncthreads();

    for (int s = 1; s < 1024; s <<= 1) {
        int v = (t >= s) ? totals[t - s] : 0;
        __syncthreads();
        totals[t] += v;
        __syncthreads();
    }

    int run = (t > 0) ? totals[t - 1] : 0;  // exclusive prefix
    for (int i = 0; i < CH; i++) {
        int idx = base + i;
        if (idx < N_NODES) {
            g_off[idx] = run;
            g_cursor[idx] = run;
            run += g_deg[idx];
        }
    }
}

__global__ __launch_bounds__(256) void scatter_kernel(
    const float* __restrict__ weight,
    const int* __restrict__ src, const int* __restrict__ dst, int nedges)
{
    int e = blockIdx.x * 256 + threadIdx.x;
    if (e >= nedges) return;
    int s = src[e];
    int d = dst[e];
    if ((unsigned)s >= N_NODES || (unsigned)d >= N_NODES) return;
    int pos = atomicAdd(&g_cursor[d], 1);
    g_csr[pos] = make_int2(s, __float_as_int(weight[e]));
}

// ---------------------------------------------------------------------------
// Aggregate: one warp per node; 4-way edge unroll for MLP=4 on the L2 gathers.
// ---------------------------------------------------------------------------
__device__ __forceinline__ void fmax4(float4& acc, float4 v, float w) {
    acc.x = fmaxf(acc.x, v.x * w);
    acc.y = fmaxf(acc.y, v.y * w);
    acc.z = fmaxf(acc.z, v.z * w);
    acc.w = fmaxf(acc.w, v.w * w);
}

__global__ __launch_bounds__(256) void aggregate_kernel()
{
    int n = blockIdx.x * 8 + (threadIdx.x >> 5);
    if (n >= N_NODES) return;
    int lane = threadIdx.x & 31;

    int off = g_off[n];
    int deg = g_deg[n];

    float4 acc = make_float4(-CUDART_INF_F, -CUDART_INF_F, -CUDART_INF_F, -CUDART_INF_F);

    int j = 0;
    for (; j + 4 <= deg; j += 4) {
        int2 e0 = g_csr[off + j + 0];
        int2 e1 = g_csr[off + j + 1];
        int2 e2 = g_csr[off + j + 2];
        int2 e3 = g_csr[off + j + 3];
        float4 v0 = *reinterpret_cast<const float4*>(&g_h[(size_t)e0.x * D + lane * 4]);
        float4 v1 = *reinterpret_cast<const float4*>(&g_h[(size_t)e1.x * D + lane * 4]);
        float4 v2 = *reinterpret_cast<const float4*>(&g_h[(size_t)e2.x * D + lane * 4]);
        float4 v3 = *reinterpret_cast<const float4*>(&g_h[(size_t)e3.x * D + lane * 4]);
        fmax4(acc, v0, __int_as_float(e0.y));
        fmax4(acc, v1, __int_as_float(e1.y));
        fmax4(acc, v2, __int_as_float(e2.y));
        fmax4(acc, v3, __int_as_float(e3.y));
    }
    for (; j < deg; j++) {
        int2 e = g_csr[off + j];
        float4 v = *reinterpret_cast<const float4*>(&g_h[(size_t)e.x * D + lane * 4]);
        fmax4(acc, v, __int_as_float(e.y));
    }
    if (deg == 0) acc = make_float4(0.f, 0.f, 0.f, 0.f);
    *reinterpret_cast<float4*>(&g_neighf[(size_t)n * D + lane * 4]) = acc;
}

extern "C" void kernel_launch(void* const* d_in, const int* in_sizes, int n_in,
                              void* d_out, int out_size)
{
    const float* feat   = (const float*)d_in[0];
    const float* weight = (const float*)d_in[1];
    const int*   src    = (const int*)d_in[2];
    const int*   dst    = (const int*)d_in[3];
    const float* Wp     = (const float*)d_in[4];
    const float* bp     = (const float*)d_in[5];
    const float* Wn     = (const float*)d_in[6];
    const float* bn     = (const float*)d_in[7];
    float* out = (float*)d_out;

    void* deg_ptr = nullptr;
    cudaGetSymbolAddress(&deg_ptr, g_deg);
    cudaMemsetAsync(deg_ptr, 0, sizeof(int) * N_NODES);

    int grid_rows = (N_NODES + 127) / 128;        // 391
    gemm_pool<<<grid_rows, 256>>>(feat, Wp, bp, N_NODES);

    int eb = (N_EDGES + 255) / 256;               // 2500
    hist_kernel<<<eb, 256>>>(dst, N_EDGES);
    scan_kernel<<<1, 1024>>>();
    scatter_kernel<<<eb, 256>>>(weight, src, dst, N_EDGES);

    aggregate_kernel<<<(N_NODES + 7) / 8, 256>>>();

    gemm_out<<<grid_rows, 256>>>(feat, Wn, bn, out, N_NODES);
}

// round 8
// speedup vs baseline: 1.3167x; 1.0774x over previous
#include <cuda_runtime.h>
#include <cstdint>
#include <math_constants.h>

#define N_NODES 50000
#define N_EDGES 640000
#define D 128
#define OUT 128

// Scratch (no allocs allowed)
__device__ float g_h[(size_t)N_NODES * D];       // feat @ Wp.T
__device__ float g_neighf[(size_t)N_NODES * D];  // segment-max result
__device__ int   g_deg[N_NODES];
__device__ int   g_off[N_NODES];
__device__ int   g_cursor[N_NODES];
__device__ int2  g_csr[N_EDGES];                 // packed {src, weight-bits}

// Packed f32x2 FMA: d = a*b + c on both halves (sm_100+; ptxas never emits
// FFMA2 from C++ — PTX-only path, 2x fp32 FMA throughput).
#define FMA_F32X2(acc, a2, b2) \
    asm("fma.rn.f32x2 %0, %1, %2, %0;" : "+l"(acc) : "l"(a2), "l"(b2))
#define DUP_F32X2(dst, f) \
    asm("mov.b64 %0, {%1, %1};" : "=l"(dst) : "f"(f))
#define UNPACK_F32X2_(lo, hi, p) \
    asm("mov.b64 {%0, %1}, %2;" : "=f"(lo), "=f"(hi) : "l"(p))

// ---------------------------------------------------------------------------
// GEMM: 128x128 block tile, 256 threads, 8x8 micro-tile, k-major smem,
// FFMA2 accumulation (32 packed b64 accumulators / thread).
// ---------------------------------------------------------------------------
#define KC 16
#define STRA 132   // padded k-major row stride in floats (16B aligned)

// GEMM1: g_h[n][o] = sum_k feat[n][k]*Wp[o][k] + bp[o]   (K = 128)
__global__ __launch_bounds__(256) void gemm_pool(
    const float* __restrict__ feat, const float* __restrict__ Wp,
    const float* __restrict__ bp, int nrows)
{
    __shared__ __align__(16) float As[KC][STRA];
    __shared__ __align__(16) float Bs[KC][STRA];

    const int tid = threadIdx.x;
    const int tx = tid & 15;        // cols tx*4..+3 and 64+tx*4..+3
    const int ty = tid >> 4;        // rows ty*8..+7
    const int row0 = blockIdx.x * 128;

    unsigned long long acc2[8][4];
#pragma unroll
    for (int i = 0; i < 8; i++)
#pragma unroll
        for (int p = 0; p < 4; p++) acc2[i][p] = 0ULL;

    for (int c = 0; c < 8; c++) {
#pragma unroll
        for (int t = 0; t < 2; t++) {
            int idx = tid + t * 256;
            int row = idx >> 2, kq = idx & 3;
            float4 v = make_float4(0.f, 0.f, 0.f, 0.f);
            if (row0 + row < nrows)
                v = *reinterpret_cast<const float4*>(&feat[(size_t)(row0 + row) * D + c * KC + kq * 4]);
            As[kq * 4 + 0][row] = v.x; As[kq * 4 + 1][row] = v.y;
            As[kq * 4 + 2][row] = v.z; As[kq * 4 + 3][row] = v.w;
        }
#pragma unroll
        for (int t = 0; t < 2; t++) {
            int idx = tid + t * 256;
            int o = idx >> 2, kq = idx & 3;
            float4 v = *reinterpret_cast<const float4*>(&Wp[(size_t)o * D + c * KC + kq * 4]);
            Bs[kq * 4 + 0][o] = v.x; Bs[kq * 4 + 1][o] = v.y;
            Bs[kq * 4 + 2][o] = v.z; Bs[kq * 4 + 3][o] = v.w;
        }
        __syncthreads();

#pragma unroll
        for (int kk = 0; kk < KC; kk++) {
            float4 a0 = *reinterpret_cast<const float4*>(&As[kk][ty * 8]);
            float4 a1 = *reinterpret_cast<const float4*>(&As[kk][ty * 8 + 4]);
            ulonglong2 bl0 = *reinterpret_cast<const ulonglong2*>(&Bs[kk][tx * 4]);
            ulonglong2 bl1 = *reinterpret_cast<const ulonglong2*>(&Bs[kk][64 + tx * 4]);
            unsigned long long bp2[4] = {bl0.x, bl0.y, bl1.x, bl1.y};
            float a[8] = {a0.x, a0.y, a0.z, a0.w, a1.x, a1.y, a1.z, a1.w};
            unsigned long long ad[8];
#pragma unroll
            for (int i = 0; i < 8; i++) DUP_F32X2(ad[i], a[i]);
#pragma unroll
            for (int i = 0; i < 8; i++)
#pragma unroll
                for (int p = 0; p < 4; p++) FMA_F32X2(acc2[i][p], ad[i], bp2[p]);
        }
        __syncthreads();
    }

#pragma unroll
    for (int i = 0; i < 8; i++) {
        int row = row0 + ty * 8 + i;
        if (row >= nrows) continue;
        float cv[8];
#pragma unroll
        for (int p = 0; p < 4; p++) UNPACK_F32X2_(cv[2 * p], cv[2 * p + 1], acc2[i][p]);
        float4 r0, r1;
        r0.x = cv[0] + bp[tx * 4 + 0];  r0.y = cv[1] + bp[tx * 4 + 1];
        r0.z = cv[2] + bp[tx * 4 + 2];  r0.w = cv[3] + bp[tx * 4 + 3];
        r1.x = cv[4] + bp[64 + tx * 4 + 0]; r1.y = cv[5] + bp[64 + tx * 4 + 1];
        r1.z = cv[6] + bp[64 + tx * 4 + 2]; r1.w = cv[7] + bp[64 + tx * 4 + 3];
        *reinterpret_cast<float4*>(&g_h[(size_t)row * D + tx * 4]) = r0;
        *reinterpret_cast<float4*>(&g_h[(size_t)row * D + 64 + tx * 4]) = r1;
    }
}

// GEMM2: out[n][o] = sum_{k<256} cat(feat,neigh)[n][k]*Wn[o][k] + bn[o]
__global__ __launch_bounds__(256) void gemm_out(
    const float* __restrict__ feat, const float* __restrict__ Wn,
    const float* __restrict__ bn, float* __restrict__ out, int nrows)
{
    __shared__ __align__(16) float As[KC][STRA];
    __shared__ __align__(16) float Bs[KC][STRA];

    const int tid = threadIdx.x;
    const int tx = tid & 15;
    const int ty = tid >> 4;
    const int row0 = blockIdx.x * 128;

    unsigned long long acc2[8][4];
#pragma unroll
    for (int i = 0; i < 8; i++)
#pragma unroll
        for (int p = 0; p < 4; p++) acc2[i][p] = 0ULL;

    for (int c = 0; c < 16; c++) {
        const float* Asrc = (c < 8) ? feat : g_neighf;
        int kbase = (c < 8) ? c * KC : (c - 8) * KC;
#pragma unroll
        for (int t = 0; t < 2; t++) {
            int idx = tid + t * 256;
            int row = idx >> 2, kq = idx & 3;
            float4 v = make_float4(0.f, 0.f, 0.f, 0.f);
            if (row0 + row < nrows)
                v = *reinterpret_cast<const float4*>(&Asrc[(size_t)(row0 + row) * D + kbase + kq * 4]);
            As[kq * 4 + 0][row] = v.x; As[kq * 4 + 1][row] = v.y;
            As[kq * 4 + 2][row] = v.z; As[kq * 4 + 3][row] = v.w;
        }
#pragma unroll
        for (int t = 0; t < 2; t++) {
            int idx = tid + t * 256;
            int o = idx >> 2, kq = idx & 3;
            float4 v = *reinterpret_cast<const float4*>(&Wn[(size_t)o * 256 + c * KC + kq * 4]);
            Bs[kq * 4 + 0][o] = v.x; Bs[kq * 4 + 1][o] = v.y;
            Bs[kq * 4 + 2][o] = v.z; Bs[kq * 4 + 3][o] = v.w;
        }
        __syncthreads();

#pragma unroll
        for (int kk = 0; kk < KC; kk++) {
            float4 a0 = *reinterpret_cast<const float4*>(&As[kk][ty * 8]);
            float4 a1 = *reinterpret_cast<const float4*>(&As[kk][ty * 8 + 4]);
            ulonglong2 bl0 = *reinterpret_cast<const ulonglong2*>(&Bs[kk][tx * 4]);
            ulonglong2 bl1 = *reinterpret_cast<const ulonglong2*>(&Bs[kk][64 + tx * 4]);
            unsigned long long bp2[4] = {bl0.x, bl0.y, bl1.x, bl1.y};
            float a[8] = {a0.x, a0.y, a0.z, a0.w, a1.x, a1.y, a1.z, a1.w};
            unsigned long long ad[8];
#pragma unroll
            for (int i = 0; i < 8; i++) DUP_F32X2(ad[i], a[i]);
#pragma unroll
            for (int i = 0; i < 8; i++)
#pragma unroll
                for (int p = 0; p < 4; p++) FMA_F32X2(acc2[i][p], ad[i], bp2[p]);
        }
        __syncthreads();
    }

#pragma unroll
    for (int i = 0; i < 8; i++) {
        int row = row0 + ty * 8 + i;
        if (row >= nrows) continue;
        float cv[8];
#pragma unroll
        for (int p = 0; p < 4; p++) UNPACK_F32X2_(cv[2 * p], cv[2 * p + 1], acc2[i][p]);
        float4 r0, r1;
        r0.x = cv[0] + bn[tx * 4 + 0];  r0.y = cv[1] + bn[tx * 4 + 1];
        r0.z = cv[2] + bn[tx * 4 + 2];  r0.w = cv[3] + bn[tx * 4 + 3];
        r1.x = cv[4] + bn[64 + tx * 4 + 0]; r1.y = cv[5] + bn[64 + tx * 4 + 1];
        r1.z = cv[6] + bn[64 + tx * 4 + 2]; r1.w = cv[7] + bn[64 + tx * 4 + 3];
        *reinterpret_cast<float4*>(&out[(size_t)row * OUT + tx * 4]) = r0;
        *reinterpret_cast<float4*>(&out[(size_t)row * OUT + 64 + tx * 4]) = r1;
    }
}

// ---------------------------------------------------------------------------
// CSR build: histogram -> scan -> scatter
// ---------------------------------------------------------------------------
__global__ __launch_bounds__(256) void hist_kernel(const int* __restrict__ dst, int nedges)
{
    int e = blockIdx.x * 256 + threadIdx.x;
    if (e >= nedges) return;
    int d = dst[e];
    if ((unsigned)d < N_NODES) atomicAdd(&g_deg[d], 1);
}

__global__ __launch_bounds__(1024) void scan_kernel()
{
    __shared__ int totals[1024];
    const int CH = (N_NODES + 1023) / 1024;  // 49
    int t = threadIdx.x;
    int base = t * CH;

    int sum = 0;
#pragma unroll
    for (int i = 0; i < CH; i++) {
        int idx = base + i;
        if (idx < N_NODES) sum += g_deg[idx];
    }
    totals[t] = sum;
    __syncthreads();

    for (int s = 1; s < 1024; s <<= 1) {
        int v = (t >= s) ? totals[t - s] : 0;
        __syncthreads();
        totals[t] += v;
        __syncthreads();
    }

    int run = (t > 0) ? totals[t - 1] : 0;  // exclusive prefix
    for (int i = 0; i < CH; i++) {
        int idx = base + i;
        if (idx < N_NODES) {
            g_off[idx] = run;
            g_cursor[idx] = run;
            run += g_deg[idx];
        }
    }
}

__global__ __launch_bounds__(256) void scatter_kernel(
    const float* __restrict__ weight,
    const int* __restrict__ src, const int* __restrict__ dst, int nedges)
{
    int e = blockIdx.x * 256 + threadIdx.x;
    if (e >= nedges) return;
    int s = src[e];
    int d = dst[e];
    if ((unsigned)s >= N_NODES || (unsigned)d >= N_NODES) return;
    int pos = atomicAdd(&g_cursor[d], 1);
    g_csr[pos] = make_int2(s, __float_as_int(weight[e]));
}

// ---------------------------------------------------------------------------
// Aggregate: one warp per node. Lane-parallel CSR preload (32 edges/window),
// shfl broadcast, predicated 8-wide gather batches (MLP=8). No atomics.
// ---------------------------------------------------------------------------
__device__ __forceinline__ void fmax4(float4& acc, float4 v, float w) {
    acc.x = fmaxf(acc.x, v.x * w);
    acc.y = fmaxf(acc.y, v.y * w);
    acc.z = fmaxf(acc.z, v.z * w);
    acc.w = fmaxf(acc.w, v.w * w);
}

__global__ __launch_bounds__(256) void aggregate_kernel()
{
    int n = blockIdx.x * 8 + (threadIdx.x >> 5);
    if (n >= N_NODES) return;
    int lane = threadIdx.x & 31;

    int off = g_off[n];
    int deg = g_deg[n];

    float4 acc = make_float4(-CUDART_INF_F, -CUDART_INF_F, -CUDART_INF_F, -CUDART_INF_F);

    for (int base = 0; base < deg; base += 32) {
        int cnt = deg - base; if (cnt > 32) cnt = 32;
        int2 e = make_int2(0, 0);
        if (lane < cnt) e = g_csr[off + base + lane];

        for (int jb = 0; jb < cnt; jb += 8) {
            float4 v[8]; float w[8]; bool val[8];
#pragma unroll
            for (int u = 0; u < 8; u++) {
                int idx = jb + u;
                val[u] = idx < cnt;
                int idc = val[u] ? idx : 0;
                int s = __shfl_sync(0xffffffffu, e.x, idc);
                w[u] = __int_as_float(__shfl_sync(0xffffffffu, e.y, idc));
                v[u] = *reinterpret_cast<const float4*>(&g_h[(size_t)s * D + lane * 4]);
            }
#pragma unroll
            for (int u = 0; u < 8; u++)
                if (val[u]) fmax4(acc, v[u], w[u]);
        }
    }
    if (deg == 0) acc = make_float4(0.f, 0.f, 0.f, 0.f);
    *reinterpret_cast<float4*>(&g_neighf[(size_t)n * D + lane * 4]) = acc;
}

extern "C" void kernel_launch(void* const* d_in, const int* in_sizes, int n_in,
                              void* d_out, int out_size)
{
    const float* feat   = (const float*)d_in[0];
    const float* weight = (const float*)d_in[1];
    const int*   src    = (const int*)d_in[2];
    const int*   dst    = (const int*)d_in[3];
    const float* Wp     = (const float*)d_in[4];
    const float* bp     = (const float*)d_in[5];
    const float* Wn     = (const float*)d_in[6];
    const float* bn     = (const float*)d_in[7];
    float* out = (float*)d_out;

    void* deg_ptr = nullptr;
    cudaGetSymbolAddress(&deg_ptr, g_deg);
    cudaMemsetAsync(deg_ptr, 0, sizeof(int) * N_NODES);

    int grid_rows = (N_NODES + 127) / 128;        // 391
    gemm_pool<<<grid_rows, 256>>>(feat, Wp, bp, N_NODES);

    int eb = (N_EDGES + 255) / 256;               // 2500
    hist_kernel<<<eb, 256>>>(dst, N_EDGES);
    scan_kernel<<<1, 1024>>>();
    scatter_kernel<<<eb, 256>>>(weight, src, dst, N_EDGES);

    aggregate_kernel<<<(N_NODES + 7) / 8, 256>>>();

    gemm_out<<<grid_rows, 256>>>(feat, Wn, bn, out, N_NODES);
}

// round 9
// speedup vs baseline: 1.5736x; 1.1952x over previous
#include <cuda_runtime.h>
#include <cuda_bf16.h>
#include <cstdint>
#include <math_constants.h>

#define N_NODES 50000
#define N_EDGES 640000
#define D 128
#define OUT 128

// Scratch (no allocs allowed)
__device__ float g_h[(size_t)N_NODES * D];       // feat @ Wp.T
__device__ float g_neighf[(size_t)N_NODES * D];  // segment-max result
__device__ int   g_deg[N_NODES];
__device__ int   g_off[N_NODES];
__device__ int   g_cursor[N_NODES];
__device__ int2  g_csr[N_EDGES];                 // packed {src, weight-bits}

// ---------------------------------------------------------------------------
// Tensor-core GEMM machinery: bf16 hi/lo split, m16n8k16 HMMA, fp32 accum.
// Smem: k-major bf16x2 words, row stride 20 words (80B) -> ldmatrix
// conflict-free (20*r mod 32 spans all banks over 8 rows).
// ---------------------------------------------------------------------------
#define STR 20   // words per row

__device__ __forceinline__ void split2(float x, float y, unsigned& hi, unsigned& lo) {
    __nv_bfloat162 h = __floats2bfloat162_rn(x, y);
    float hx = __bfloat162float(h.x), hy = __bfloat162float(h.y);
    __nv_bfloat162 l = __floats2bfloat162_rn(x - hx, y - hy);
    hi = *reinterpret_cast<unsigned*>(&h);
    lo = *reinterpret_cast<unsigned*>(&l);
}

__device__ __forceinline__ void ldmx4(unsigned* r, unsigned addr) {
    asm volatile("ldmatrix.sync.aligned.m8n8.x4.shared.b16 {%0,%1,%2,%3}, [%4];"
                 : "=r"(r[0]), "=r"(r[1]), "=r"(r[2]), "=r"(r[3]) : "r"(addr));
}
__device__ __forceinline__ void ldmx2(unsigned* r, unsigned addr) {
    asm volatile("ldmatrix.sync.aligned.m8n8.x2.shared.b16 {%0,%1}, [%2];"
                 : "=r"(r[0]), "=r"(r[1]) : "r"(addr));
}
__device__ __forceinline__ void mma16816(float* d, const unsigned* a, const unsigned* b) {
    asm volatile("mma.sync.aligned.m16n8k16.row.col.f32.bf16.bf16.f32 "
                 "{%0,%1,%2,%3}, {%4,%5,%6,%7}, {%8,%9}, {%0,%1,%2,%3};"
                 : "+f"(d[0]), "+f"(d[1]), "+f"(d[2]), "+f"(d[3])
                 : "r"(a[0]), "r"(a[1]), "r"(a[2]), "r"(a[3]), "r"(b[0]), "r"(b[1]));
}

// Generic 128x128-tile split-bf16 GEMM body. KCH = number of 32-wide K chunks.
// getA(row, chunk) -> const float* base of 32 floats; B row-major [128][Ktot].
template <int KCH>
__device__ __forceinline__ void gemm_body(
    const float* __restrict__ A0, const float* __restrict__ A1, int a1_chunk0,
    int strideA,
    const float* __restrict__ B, int strideB,
    const float* __restrict__ bias, float* __restrict__ Cout, int strideC,
    int nrows)
{
    __shared__ unsigned Ahi[128 * STR], Alo[128 * STR];
    __shared__ unsigned Bhi[128 * STR], Blo[128 * STR];

    const int tid = threadIdx.x;
    const int lane = tid & 31;
    const int wid = tid >> 5;
    const int wm = wid & 1;        // 2 m-groups of 64 rows
    const int wn = wid >> 1;       // 4 n-groups of 32 cols
    const int row0 = blockIdx.x * 128;

    // ldmatrix per-lane address components
    const int lr = lane & 7;
    const int grpA = lane >> 3;
    const int rowA = lr + (grpA & 1) * 8;
    const int wordA = (grpA >> 1) * 4;
    const int grpB = (lane >> 3) & 1;
    const int wordB = grpB * 4;

    const unsigned baseAhi = (unsigned)__cvta_generic_to_shared(Ahi);
    const unsigned baseAlo = (unsigned)__cvta_generic_to_shared(Alo);
    const unsigned baseBhi = (unsigned)__cvta_generic_to_shared(Bhi);
    const unsigned baseBlo = (unsigned)__cvta_generic_to_shared(Blo);

    float acc[4][4][4];
#pragma unroll
    for (int i = 0; i < 4; i++)
#pragma unroll
        for (int j = 0; j < 4; j++)
#pragma unroll
            for (int r = 0; r < 4; r++) acc[i][j][r] = 0.0f;

    for (int c = 0; c < KCH; c++) {
        const float* Asrc = (c < a1_chunk0) ? A0 : A1;
        const int akb = (c < a1_chunk0) ? c * 32 : (c - a1_chunk0) * 32;

        // A tile: 128 rows x 32 k  (1024 float4 / 256 thr = 4 each)
#pragma unroll
        for (int t = 0; t < 4; t++) {
            int idx = tid + t * 256;
            int row = idx >> 3, q = idx & 7;
            float4 v = make_float4(0.f, 0.f, 0.f, 0.f);
            if (row0 + row < nrows)
                v = *reinterpret_cast<const float4*>(&Asrc[(size_t)(row0 + row) * strideA + akb + q * 4]);
            unsigned h0, l0, h1, l1;
            split2(v.x, v.y, h0, l0);
            split2(v.z, v.w, h1, l1);
            int sb = row * STR + q * 2;
            Ahi[sb] = h0; Ahi[sb + 1] = h1;
            Alo[sb] = l0; Alo[sb + 1] = l1;
        }
        // B tile: 128 outs x 32 k
#pragma unroll
        for (int t = 0; t < 4; t++) {
            int idx = tid + t * 256;
            int o = idx >> 3, q = idx & 7;
            float4 v = *reinterpret_cast<const float4*>(&B[(size_t)o * strideB + c * 32 + q * 4]);
            unsigned h0, l0, h1, l1;
            split2(v.x, v.y, h0, l0);
            split2(v.z, v.w, h1, l1);
            int sb = o * STR + q * 2;
            Bhi[sb] = h0; Bhi[sb + 1] = h1;
            Blo[sb] = l0; Blo[sb + 1] = l1;
        }
        __syncthreads();

#pragma unroll
        for (int s = 0; s < 2; s++) {
            unsigned ahi[4][4], alo[4][4];
#pragma unroll
            for (int tm = 0; tm < 4; tm++) {
                unsigned off = ((wm * 64 + tm * 16 + rowA) * STR + s * 8 + wordA) * 4u;
                ldmx4(ahi[tm], baseAhi + off);
                ldmx4(alo[tm], baseAlo + off);
            }
            unsigned bhi[4][2], blo[4][2];
#pragma unroll
            for (int tn = 0; tn < 4; tn++) {
                unsigned off = ((wn * 32 + tn * 8 + lr) * STR + s * 8 + wordB) * 4u;
                ldmx2(bhi[tn], baseBhi + off);
                ldmx2(blo[tn], baseBlo + off);
            }
#pragma unroll
            for (int tm = 0; tm < 4; tm++)
#pragma unroll
                for (int tn = 0; tn < 4; tn++) {
                    mma16816(acc[tm][tn], ahi[tm], bhi[tn]);
                    mma16816(acc[tm][tn], ahi[tm], blo[tn]);
                    mma16816(acc[tm][tn], alo[tm], bhi[tn]);
                }
        }
        __syncthreads();
    }

    // Epilogue: c0,c1 -> (row, col..col+1); c2,c3 -> (row+8, ...)
#pragma unroll
    for (int tm = 0; tm < 4; tm++) {
#pragma unroll
        for (int tn = 0; tn < 4; tn++) {
            int col = wn * 32 + tn * 8 + (lane & 3) * 2;
            float b0 = bias[col], b1 = bias[col + 1];
            int r1 = row0 + wm * 64 + tm * 16 + (lane >> 2);
            if (r1 < nrows) {
                float2 v = make_float2(acc[tm][tn][0] + b0, acc[tm][tn][1] + b1);
                *reinterpret_cast<float2*>(&Cout[(size_t)r1 * strideC + col]) = v;
            }
            int r2 = r1 + 8;
            if (r2 < nrows) {
                float2 v = make_float2(acc[tm][tn][2] + b0, acc[tm][tn][3] + b1);
                *reinterpret_cast<float2*>(&Cout[(size_t)r2 * strideC + col]) = v;
            }
        }
    }
}

// GEMM1: g_h = feat @ Wp.T + bp   (K=128 -> 4 chunks)
__global__ __launch_bounds__(256) void gemm_pool(
    const float* __restrict__ feat, const float* __restrict__ Wp,
    const float* __restrict__ bp, int nrows)
{
    gemm_body<4>(feat, feat, 4, D, Wp, D, bp, g_h, D, nrows);
}

// GEMM2: out = [feat | neigh] @ Wn.T + bn   (K=256 -> 8 chunks; last 4 from neigh)
__global__ __launch_bounds__(256) void gemm_out(
    const float* __restrict__ feat, const float* __restrict__ Wn,
    const float* __restrict__ bn, float* __restrict__ out, int nrows)
{
    gemm_body<8>(feat, g_neighf, 4, D, Wn, 256, bn, out, OUT, nrows);
}

// ---------------------------------------------------------------------------
// CSR build: histogram -> scan -> scatter
// ---------------------------------------------------------------------------
__global__ __launch_bounds__(256) void hist_kernel(const int* __restrict__ dst, int nedges)
{
    int e = blockIdx.x * 256 + threadIdx.x;
    if (e >= nedges) return;
    int d = dst[e];
    if ((unsigned)d < N_NODES) atomicAdd(&g_deg[d], 1);
}

__global__ __launch_bounds__(1024) void scan_kernel()
{
    __shared__ int totals[1024];
    const int CH = (N_NODES + 1023) / 1024;  // 49
    int t = threadIdx.x;
    int base = t * CH;

    int sum = 0;
#pragma unroll
    for (int i = 0; i < CH; i++) {
        int idx = base + i;
        if (idx < N_NODES) sum += g_deg[idx];
    }
    totals[t] = sum;
    __syncthreads();

    for (int s = 1; s < 1024; s <<= 1) {
        int v = (t >= s) ? totals[t - s] : 0;
        __syncthreads();
        totals[t] += v;
        __syncthreads();
    }

    int run = (t > 0) ? totals[t - 1] : 0;  // exclusive prefix
    for (int i = 0; i < CH; i++) {
        int idx = base + i;
        if (idx < N_NODES) {
            g_off[idx] = run;
            g_cursor[idx] = run;
            run += g_deg[idx];
        }
    }
}

__global__ __launch_bounds__(256) void scatter_kernel(
    const float* __restrict__ weight,
    const int* __restrict__ src, const int* __restrict__ dst, int nedges)
{
    int e = blockIdx.x * 256 + threadIdx.x;
    if (e >= nedges) return;
    int s = src[e];
    int d = dst[e];
    if ((unsigned)s >= N_NODES || (unsigned)d >= N_NODES) return;
    int pos = atomicAdd(&g_cursor[d], 1);
    g_csr[pos] = make_int2(s, __float_as_int(weight[e]));
}

// ---------------------------------------------------------------------------
// Aggregate: one warp per node. Lane-parallel CSR preload (32 edges/window),
// shfl broadcast, predicated 8-wide gather batches (MLP=8). No atomics.
// ---------------------------------------------------------------------------
__device__ __forceinline__ void fmax4(float4& acc, float4 v, float w) {
    acc.x = fmaxf(acc.x, v.x * w);
    acc.y = fmaxf(acc.y, v.y * w);
    acc.z = fmaxf(acc.z, v.z * w);
    acc.w = fmaxf(acc.w, v.w * w);
}

__global__ __launch_bounds__(256) void aggregate_kernel()
{
    int n = blockIdx.x * 8 + (threadIdx.x >> 5);
    if (n >= N_NODES) return;
    int lane = threadIdx.x & 31;

    int off = g_off[n];
    int deg = g_deg[n];

    float4 acc = make_float4(-CUDART_INF_F, -CUDART_INF_F, -CUDART_INF_F, -CUDART_INF_F);

    for (int base = 0; base < deg; base += 32) {
        int cnt = deg - base; if (cnt > 32) cnt = 32;
        int2 e = make_int2(0, 0);
        if (lane < cnt) e = g_csr[off + base + lane];

        for (int jb = 0; jb < cnt; jb += 8) {
            float4 v[8]; float w[8]; bool val[8];
#pragma unroll
            for (int u = 0; u < 8; u++) {
                int idx = jb + u;
                val[u] = idx < cnt;
                int idc = val[u] ? idx : 0;
                int s = __shfl_sync(0xffffffffu, e.x, idc);
                w[u] = __int_as_float(__shfl_sync(0xffffffffu, e.y, idc));
                v[u] = *reinterpret_cast<const float4*>(&g_h[(size_t)s * D + lane * 4]);
            }
#pragma unroll
            for (int u = 0; u < 8; u++)
                if (val[u]) fmax4(acc, v[u], w[u]);
        }
    }
    if (deg == 0) acc = make_float4(0.f, 0.f, 0.f, 0.f);
    *reinterpret_cast<float4*>(&g_neighf[(size_t)n * D + lane * 4]) = acc;
}

extern "C" void kernel_launch(void* const* d_in, const int* in_sizes, int n_in,
                              void* d_out, int out_size)
{
    const float* feat   = (const float*)d_in[0];
    const float* weight = (const float*)d_in[1];
    const int*   src    = (const int*)d_in[2];
    const int*   dst    = (const int*)d_in[3];
    const float* Wp     = (const float*)d_in[4];
    const float* bp     = (const float*)d_in[5];
    const float* Wn     = (const float*)d_in[6];
    const float* bn     = (const float*)d_in[7];
    float* out = (float*)d_out;

    void* deg_ptr = nullptr;
    cudaGetSymbolAddress(&deg_ptr, g_deg);
    cudaMemsetAsync(deg_ptr, 0, sizeof(int) * N_NODES);

    int grid_rows = (N_NODES + 127) / 128;        // 391
    gemm_pool<<<grid_rows, 256>>>(feat, Wp, bp, N_NODES);

    int eb = (N_EDGES + 255) / 256;               // 2500
    hist_kernel<<<eb, 256>>>(dst, N_EDGES);
    scan_kernel<<<1, 1024>>>();
    scatter_kernel<<<eb, 256>>>(weight, src, dst, N_EDGES);

    aggregate_kernel<<<(N_NODES + 7) / 8, 256>>>();

    gemm_out<<<grid_rows, 256>>>(feat, Wn, bn, out, N_NODES);
}

// round 13
// speedup vs baseline: 1.6690x; 1.0606x over previous
#include <cuda_runtime.h>
#include <cuda_bf16.h>
#include <cstdint>
#include <math_constants.h>

#define N_NODES 50000
#define N_EDGES 640000
#define D 128
#define OUT 128

// Scratch (no device allocs allowed)
__device__ float    g_h[(size_t)N_NODES * D];        // feat @ Wp.T (fp32, for aggregate)
__device__ int      g_deg[N_NODES];
__device__ int      g_off[N_NODES];
__device__ int      g_cursor[N_NODES];
__device__ int2     g_csr[N_EDGES];                  // packed {src, weight-bits}
// bf16 hi/lo planes (bf16x2 words, k-major pairs)
__device__ unsigned g_feat_hi[(size_t)N_NODES * 64], g_feat_lo[(size_t)N_NODES * 64];
__device__ unsigned g_neigh_hi[(size_t)N_NODES * 64], g_neigh_lo[(size_t)N_NODES * 64];
__device__ unsigned g_wp_hi[128 * 64],  g_wp_lo[128 * 64];
__device__ unsigned g_wn_hi[128 * 128], g_wn_lo[128 * 128];

__device__ __forceinline__ void split2(float x, float y, unsigned& hi, unsigned& lo) {
    __nv_bfloat162 h = __floats2bfloat162_rn(x, y);
    float hx = __bfloat162float(h.x), hy = __bfloat162float(h.y);
    __nv_bfloat162 l = __floats2bfloat162_rn(x - hx, y - hy);
    hi = *reinterpret_cast<unsigned*>(&h);
    lo = *reinterpret_cast<unsigned*>(&l);
}

// ---------------------------------------------------------------------------
// Split kernels: fp32 -> bf16 hi/lo planes (one float4 -> one uint2 per plane)
// ---------------------------------------------------------------------------
__global__ __launch_bounds__(256) void split_kernel(
    const float* __restrict__ src, unsigned* __restrict__ hi,
    unsigned* __restrict__ lo, int nquad)
{
    int idx = blockIdx.x * 256 + threadIdx.x;
    if (idx >= nquad) return;
    float4 v = *reinterpret_cast<const float4*>(&src[(size_t)idx * 4]);
    unsigned h0, l0, h1, l1;
    split2(v.x, v.y, h0, l0);
    split2(v.z, v.w, h1, l1);
    *reinterpret_cast<uint2*>(&hi[(size_t)idx * 2]) = make_uint2(h0, h1);
    *reinterpret_cast<uint2*>(&lo[(size_t)idx * 2]) = make_uint2(l0, l1);
}

// ---------------------------------------------------------------------------
// Tensor-core GEMM: pre-split bf16 planes, m16n8k16 HMMA, fp32 accum.
// Smem rows stride 20 words -> conflict-free ldmatrix.
// ---------------------------------------------------------------------------
#define STR 20

__device__ __forceinline__ void ldmx4(unsigned* r, unsigned addr) {
    asm volatile("ldmatrix.sync.aligned.m8n8.x4.shared.b16 {%0,%1,%2,%3}, [%4];"
                 : "=r"(r[0]), "=r"(r[1]), "=r"(r[2]), "=r"(r[3]) : "r"(addr));
}
__device__ __forceinline__ void ldmx2(unsigned* r, unsigned addr) {
    asm volatile("ldmatrix.sync.aligned.m8n8.x2.shared.b16 {%0,%1}, [%2];"
                 : "=r"(r[0]), "=r"(r[1]) : "r"(addr));
}
__device__ __forceinline__ void mma16816(float* d, const unsigned* a, const unsigned* b) {
    asm volatile("mma.sync.aligned.m16n8k16.row.col.f32.bf16.bf16.f32 "
                 "{%0,%1,%2,%3}, {%4,%5,%6,%7}, {%8,%9}, {%0,%1,%2,%3};"
                 : "+f"(d[0]), "+f"(d[1]), "+f"(d[2]), "+f"(d[3])
                 : "r"(a[0]), "r"(a[1]), "r"(a[2]), "r"(a[3]), "r"(b[0]), "r"(b[1]));
}

// KCH 32-wide K chunks. A from planes (stride strAw words/row); chunk >= a1c0
// switches A plane source. B planes stride strBw words/row.
template <int KCH>
__device__ __forceinline__ void gemm_body(
    const unsigned* __restrict__ A0hi, const unsigned* __restrict__ A0lo,
    const unsigned* __restrict__ A1hi, const unsigned* __restrict__ A1lo,
    int a1c0, int strAw,
    const unsigned* __restrict__ Bhi_g, const unsigned* __restrict__ Blo_g, int strBw,
    const float* __restrict__ bias, float* __restrict__ Cout, int strideC,
    int nrows)
{
    __shared__ unsigned Ahi[128 * STR], Alo[128 * STR];
    __shared__ unsigned Bhi[128 * STR], Blo[128 * STR];

    const int tid = threadIdx.x;
    const int lane = tid & 31;
    const int wid = tid >> 5;
    const int wm = wid & 1;
    const int wn = wid >> 1;
    const int row0 = blockIdx.x * 128;

    const int lr = lane & 7;
    const int grpA = lane >> 3;
    const int rowA = lr + (grpA & 1) * 8;
    const int wordA = (grpA >> 1) * 4;
    const int wordB = ((lane >> 3) & 1) * 4;

    const unsigned baseAhi = (unsigned)__cvta_generic_to_shared(Ahi);
    const unsigned baseAlo = (unsigned)__cvta_generic_to_shared(Alo);
    const unsigned baseBhi = (unsigned)__cvta_generic_to_shared(Bhi);
    const unsigned baseBlo = (unsigned)__cvta_generic_to_shared(Blo);

    float acc[4][4][4];
#pragma unroll
    for (int i = 0; i < 4; i++)
#pragma unroll
        for (int j = 0; j < 4; j++)
#pragma unroll
            for (int r = 0; r < 4; r++) acc[i][j][r] = 0.0f;

    for (int c = 0; c < KCH; c++) {
        const unsigned* AhiS = (c < a1c0) ? A0hi : A1hi;
        const unsigned* AloS = (c < a1c0) ? A0lo : A1lo;
        const int akw = ((c < a1c0) ? c : (c - a1c0)) * 16;   // words

        // A tile: 128 rows x 16 words; 512 uint4 over 256 threads (2 each/plane)
#pragma unroll
        for (int t = 0; t < 2; t++) {
            int idx = tid + t * 256;
            int row = idx >> 2, q = idx & 3;
            uint4 vh = make_uint4(0, 0, 0, 0), vl = make_uint4(0, 0, 0, 0);
            if (row0 + row < nrows) {
                size_t go = (size_t)(row0 + row) * strAw + akw + q * 4;
                vh = *reinterpret_cast<const uint4*>(&AhiS[go]);
                vl = *reinterpret_cast<const uint4*>(&AloS[go]);
            }
            int sb = row * STR + q * 4;
            *reinterpret_cast<uint4*>(&Ahi[sb]) = vh;
            *reinterpret_cast<uint4*>(&Alo[sb]) = vl;
        }
        // B tile: 128 outs x 16 words
#pragma unroll
        for (int t = 0; t < 2; t++) {
            int idx = tid + t * 256;
            int o = idx >> 2, q = idx & 3;
            size_t go = (size_t)o * strBw + c * 16 + q * 4;
            uint4 vh = *reinterpret_cast<const uint4*>(&Bhi_g[go]);
            uint4 vl = *reinterpret_cast<const uint4*>(&Blo_g[go]);
            int sb = o * STR + q * 4;
            *reinterpret_cast<uint4*>(&Bhi[sb]) = vh;
            *reinterpret_cast<uint4*>(&Blo[sb]) = vl;
        }
        __syncthreads();

#pragma unroll
        for (int s = 0; s < 2; s++) {
            unsigned ahi[4][4], alo[4][4];
#pragma unroll
            for (int tm = 0; tm < 4; tm++) {
                unsigned off = ((wm * 64 + tm * 16 + rowA) * STR + s * 8 + wordA) * 4u;
                ldmx4(ahi[tm], baseAhi + off);
                ldmx4(alo[tm], baseAlo + off);
            }
            unsigned bhi[4][2], blo[4][2];
#pragma unroll
            for (int tn = 0; tn < 4; tn++) {
                unsigned off = ((wn * 32 + tn * 8 + lr) * STR + s * 8 + wordB) * 4u;
                ldmx2(bhi[tn], baseBhi + off);
                ldmx2(blo[tn], baseBlo + off);
            }
#pragma unroll
            for (int tm = 0; tm < 4; tm++)
#pragma unroll
                for (int tn = 0; tn < 4; tn++) {
                    mma16816(acc[tm][tn], ahi[tm], bhi[tn]);
                    mma16816(acc[tm][tn], ahi[tm], blo[tn]);
                    mma16816(acc[tm][tn], alo[tm], bhi[tn]);
                }
        }
        __syncthreads();
    }

#pragma unroll
    for (int tm = 0; tm < 4; tm++) {
#pragma unroll
        for (int tn = 0; tn < 4; tn++) {
            int col = wn * 32 + tn * 8 + (lane & 3) * 2;
            float b0 = bias[col], b1 = bias[col + 1];
            int r1 = row0 + wm * 64 + tm * 16 + (lane >> 2);
            if (r1 < nrows) {
                float2 v = make_float2(acc[tm][tn][0] + b0, acc[tm][tn][1] + b1);
                *reinterpret_cast<float2*>(&Cout[(size_t)r1 * strideC + col]) = v;
            }
            int r2 = r1 + 8;
            if (r2 < nrows) {
                float2 v = make_float2(acc[tm][tn][2] + b0, acc[tm][tn][3] + b1);
                *reinterpret_cast<float2*>(&Cout[(size_t)r2 * strideC + col]) = v;
            }
        }
    }
}

__global__ __launch_bounds__(256) void gemm_pool(const float* __restrict__ bp, int nrows)
{
    gemm_body<4>(g_feat_hi, g_feat_lo, g_feat_hi, g_feat_lo, 4, 64,
                 g_wp_hi, g_wp_lo, 64, bp, g_h, D, nrows);
}

__global__ __launch_bounds__(256) void gemm_out(
    const float* __restrict__ bn, float* __restrict__ out, int nrows)
{
    gemm_body<8>(g_feat_hi, g_feat_lo, g_neigh_hi, g_neigh_lo, 4, 64,
                 g_wn_hi, g_wn_lo, 128, bn, out, OUT, nrows);
}

// ---------------------------------------------------------------------------
// CSR build: histogram -> scan -> scatter
// ---------------------------------------------------------------------------
__global__ __launch_bounds__(256) void hist_kernel(const int* __restrict__ dst, int nedges)
{
    int e = blockIdx.x * 256 + threadIdx.x;
    if (e >= nedges) return;
    int d = dst[e];
    if ((unsigned)d < N_NODES) atomicAdd(&g_deg[d], 1);
}

__global__ __launch_bounds__(1024) void scan_kernel()
{
    __shared__ int totals[1024];
    const int CH = (N_NODES + 1023) / 1024;  // 49
    int t = threadIdx.x;
    int base = t * CH;

    int sum = 0;
#pragma unroll
    for (int i = 0; i < CH; i++) {
        int idx = base + i;
        if (idx < N_NODES) sum += g_deg[idx];
    }
    totals[t] = sum;
    __syncthreads();

    for (int s = 1; s < 1024; s <<= 1) {
        int v = (t >= s) ? totals[t - s] : 0;
        __syncthreads();
        totals[t] += v;
        __syncthreads();
    }

    int run = (t > 0) ? totals[t - 1] : 0;
    for (int i = 0; i < CH; i++) {
        int idx = base + i;
        if (idx < N_NODES) {
            g_off[idx] = run;
            g_cursor[idx] = run;
            run += g_deg[idx];
        }
    }
}

__global__ __launch_bounds__(256) void scatter_kernel(
    const float* __restrict__ weight,
    const int* __restrict__ src, const int* __restrict__ dst, int nedges)
{
    int e = blockIdx.x * 256 + threadIdx.x;
    if (e >= nedges) return;
    int s = src[e];
    int d = dst[e];
    if ((unsigned)s >= N_NODES || (unsigned)d >= N_NODES) return;
    int pos = atomicAdd(&g_cursor[d], 1);
    g_csr[pos] = make_int2(s, __float_as_int(weight[e]));
}

// ---------------------------------------------------------------------------
// Aggregate: one warp per node; shfl-broadcast CSR, 8-wide gather batches.
// Emits bf16 hi/lo planes directly (exact split of the fp32 max result).
// ---------------------------------------------------------------------------
__device__ __forceinline__ void fmax4(float4& acc, float4 v, float w) {
    acc.x = fmaxf(acc.x, v.x * w);
    acc.y = fmaxf(acc.y, v.y * w);
    acc.z = fmaxf(acc.z, v.z * w);
    acc.w = fmaxf(acc.w, v.w * w);
}

__global__ __launch_bounds__(256) void aggregate_kernel()
{
    int n = blockIdx.x * 8 + (threadIdx.x >> 5);
    if (n >= N_NODES) return;
    int lane = threadIdx.x & 31;

    int off = g_off[n];
    int deg = g_deg[n];

    float4 acc = make_float4(-CUDART_INF_F, -CUDART_INF_F, -CUDART_INF_F, -CUDART_INF_F);

    for (int base = 0; base < deg; base += 32) {
        int cnt = deg - base; if (cnt > 32) cnt = 32;
        int2 e = make_int2(0, 0);
        if (lane < cnt) e = g_csr[off + base + lane];

        for (int jb = 0; jb < cnt; jb += 8) {
            float4 v[8]; float w[8]; bool val[8];
#pragma unroll
            for (int u = 0; u < 8; u++) {
                int idx = jb + u;
                val[u] = idx < cnt;
                int idc = val[u] ? idx : 0;
                int s = __shfl_sync(0xffffffffu, e.x, idc);
                w[u] = __int_as_float(__shfl_sync(0xffffffffu, e.y, idc));
                v[u] = *reinterpret_cast<const float4*>(&g_h[(size_t)s * D + lane * 4]);
            }
#pragma unroll
            for (int u = 0; u < 8; u++)
                if (val[u]) fmax4(acc, v[u], w[u]);
        }
    }
    if (deg == 0) acc = make_float4(0.f, 0.f, 0.f, 0.f);

    unsigned h0, l0, h1, l1;
    split2(acc.x, acc.y, h0, l0);
    split2(acc.z, acc.w, h1, l1);
    size_t wi = (size_t)n * 64 + lane * 2;
    *reinterpret_cast<uint2*>(&g_neigh_hi[wi]) = make_uint2(h0, h1);
    *reinterpret_cast<uint2*>(&g_neigh_lo[wi]) = make_uint2(l0, l1);
}

// ---------------------------------------------------------------------------
extern "C" void kernel_launch(void* const* d_in, const int* in_sizes, int n_in,
                              void* d_out, int out_size)
{
    const float* feat   = (const float*)d_in[0];
    const float* weight = (const float*)d_in[1];
    const int*   src    = (const int*)d_in[2];
    const int*   dst    = (const int*)d_in[3];
    const float* Wp     = (const float*)d_in[4];
    const float* bp     = (const float*)d_in[5];
    const float* Wn     = (const float*)d_in[6];
    const float* bn     = (const float*)d_in[7];
    float* out = (float*)d_out;

    static cudaStream_t s1 = nullptr, s2 = nullptr;
    static cudaEvent_t evA = nullptr, ev1 = nullptr, ev2 = nullptr;
    if (!s1) {
        cudaStreamCreateWithFlags(&s1, cudaStreamNonBlocking);
        cudaStreamCreateWithFlags(&s2, cudaStreamNonBlocking);
        cudaEventCreateWithFlags(&evA, cudaEventDisableTiming);
        cudaEventCreateWithFlags(&ev1, cudaEventDisableTiming);
        cudaEventCreateWithFlags(&ev2, cudaEventDisableTiming);
    }

    void* deg_ptr = nullptr;
    cudaGetSymbolAddress(&deg_ptr, g_deg);
    unsigned *fh, *fl, *wph, *wpl, *wnh, *wnl;
    cudaGetSymbolAddress((void**)&fh,  g_feat_hi);
    cudaGetSymbolAddress((void**)&fl,  g_feat_lo);
    cudaGetSymbolAddress((void**)&wph, g_wp_hi);
    cudaGetSymbolAddress((void**)&wpl, g_wp_lo);
    cudaGetSymbolAddress((void**)&wnh, g_wn_hi);
    cudaGetSymbolAddress((void**)&wnl, g_wn_lo);

    // Fork: CSR chain on s1, split chain on s2, GEMMs on the capture stream.
    cudaEventRecord(evA, 0);

    cudaStreamWaitEvent(s1, evA, 0);
    cudaMemsetAsync(deg_ptr, 0, sizeof(int) * N_NODES, s1);
    int eb = (N_EDGES + 255) / 256;
    hist_kernel<<<eb, 256, 0, s1>>>(dst, N_EDGES);
    scan_kernel<<<1, 1024, 0, s1>>>();
    scatter_kernel<<<eb, 256, 0, s1>>>(weight, src, dst, N_EDGES);
    cudaEventRecord(ev1, s1);

    cudaStreamWaitEvent(s2, evA, 0);
    split_kernel<<<(N_NODES * 32 + 255) / 256, 256, 0, s2>>>(feat, fh, fl, N_NODES * 32);
    split_kernel<<<16, 256, 0, s2>>>(Wp, wph, wpl, 128 * 128 / 4);
    split_kernel<<<32, 256, 0, s2>>>(Wn, wnh, wnl, 128 * 256 / 4);
    cudaEventRecord(ev2, s2);

    cudaStreamWaitEvent(0, ev2, 0);
    int grid_rows = (N_NODES + 127) / 128;        // 391
    gemm_pool<<<grid_rows, 256>>>(bp, N_NODES);

    cudaStreamWaitEvent(0, ev1, 0);
    aggregate_kernel<<<(N_NODES + 7) / 8, 256>>>();

    gemm_out<<<grid_rows, 256>>>(bn, out, N_NODES);
}

// round 17
// speedup vs baseline: 1.7522x; 1.0499x over previous
#include <cuda_runtime.h>
#include <cuda_bf16.h>
#include <cstdint>
#include <math_constants.h>

#define N_NODES 50000
#define N_EDGES 640000
#define D 128
#define OUT 128

// Scratch (no device allocs allowed)
__device__ float    g_h[(size_t)N_NODES * D];        // feat @ Wp.T (fp32, for aggregate)
__device__ int      g_deg[N_NODES];
__device__ int      g_off[N_NODES];
__device__ int      g_cursor[N_NODES];
__device__ int2     g_csr[N_EDGES];                  // packed {src, weight-bits}
// bf16 hi/lo planes (bf16x2 words, k-major pairs)
__device__ unsigned g_feat_hi[(size_t)N_NODES * 64], g_feat_lo[(size_t)N_NODES * 64];
__device__ unsigned g_neigh_hi[(size_t)N_NODES * 64], g_neigh_lo[(size_t)N_NODES * 64];
__device__ unsigned g_wp_hi[128 * 64],  g_wp_lo[128 * 64];
__device__ unsigned g_wn_hi[128 * 128], g_wn_lo[128 * 128];

__device__ __forceinline__ void split2(float x, float y, unsigned& hi, unsigned& lo) {
    __nv_bfloat162 h = __floats2bfloat162_rn(x, y);
    float hx = __bfloat162float(h.x), hy = __bfloat162float(h.y);
    __nv_bfloat162 l = __floats2bfloat162_rn(x - hx, y - hy);
    hi = *reinterpret_cast<unsigned*>(&h);
    lo = *reinterpret_cast<unsigned*>(&l);
}

// ---------------------------------------------------------------------------
// Split kernels: fp32 -> bf16 hi/lo planes
// ---------------------------------------------------------------------------
__global__ __launch_bounds__(256) void split_kernel(
    const float* __restrict__ src, unsigned* __restrict__ hi,
    unsigned* __restrict__ lo, int nquad)
{
    int idx = blockIdx.x * 256 + threadIdx.x;
    if (idx >= nquad) return;
    float4 v = *reinterpret_cast<const float4*>(&src[(size_t)idx * 4]);
    unsigned h0, l0, h1, l1;
    split2(v.x, v.y, h0, l0);
    split2(v.z, v.w, h1, l1);
    *reinterpret_cast<uint2*>(&hi[(size_t)idx * 2]) = make_uint2(h0, h1);
    *reinterpret_cast<uint2*>(&lo[(size_t)idx * 2]) = make_uint2(l0, l1);
}

// ---------------------------------------------------------------------------
// Tensor-core GEMM: pre-split bf16 planes, m16n8k16 HMMA, fp32 accum.
// cp.async double-buffered tiles; smem rows stride 20 words (conflict-free).
// ---------------------------------------------------------------------------
#define STR 20
#define PLANE_B (128 * STR * 4)          // 10240 bytes per plane
#define BUF_B   (4 * PLANE_B)            // 40960 bytes per stage
#define SMEM_TOT (2 * BUF_B)             // 81920 bytes

extern __shared__ unsigned dynsmem[];

__device__ __forceinline__ void cpa16(unsigned saddr, const void* g, bool pred) {
    int sz = pred ? 16 : 0;
    asm volatile("cp.async.cg.shared.global [%0], [%1], 16, %2;"
                 :: "r"(saddr), "l"(g), "r"(sz));
}
__device__ __forceinline__ void cpa_commit() { asm volatile("cp.async.commit_group;"); }
template <int N>
__device__ __forceinline__ void cpa_wait() { asm volatile("cp.async.wait_group %0;" :: "n"(N)); }

__device__ __forceinline__ void ldmx4(unsigned* r, unsigned addr) {
    asm volatile("ldmatrix.sync.aligned.m8n8.x4.shared.b16 {%0,%1,%2,%3}, [%4];"
                 : "=r"(r[0]), "=r"(r[1]), "=r"(r[2]), "=r"(r[3]) : "r"(addr));
}
__device__ __forceinline__ void ldmx2(unsigned* r, unsigned addr) {
    asm volatile("ldmatrix.sync.aligned.m8n8.x2.shared.b16 {%0,%1}, [%2];"
                 : "=r"(r[0]), "=r"(r[1]) : "r"(addr));
}
__device__ __forceinline__ void mma16816(float* d, const unsigned* a, const unsigned* b) {
    asm volatile("mma.sync.aligned.m16n8k16.row.col.f32.bf16.bf16.f32 "
                 "{%0,%1,%2,%3}, {%4,%5,%6,%7}, {%8,%9}, {%0,%1,%2,%3};"
                 : "+f"(d[0]), "+f"(d[1]), "+f"(d[2]), "+f"(d[3])
                 : "r"(a[0]), "r"(a[1]), "r"(a[2]), "r"(a[3]), "r"(b[0]), "r"(b[1]));
}

template <int KCH>
__device__ __forceinline__ void gemm_body(
    const unsigned* __restrict__ A0hi, const unsigned* __restrict__ A0lo,
    const unsigned* __restrict__ A1hi, const unsigned* __restrict__ A1lo,
    int a1c0, int strAw,
    const unsigned* __restrict__ Bhi_g, const unsigned* __restrict__ Blo_g, int strBw,
    const float* __restrict__ bias, float* __restrict__ Cout, int strideC,
    int nrows)
{
    const int tid = threadIdx.x;
    const int lane = tid & 31;
    const int wid = tid >> 5;
    const int wm = wid & 1;
    const int wn = wid >> 1;
    const int row0 = blockIdx.x * 128;

    const int lr = lane & 7;
    const int grpA = lane >> 3;
    const int rowA = lr + (grpA & 1) * 8;
    const int wordA = (grpA >> 1) * 4;
    const int wordB = ((lane >> 3) & 1) * 4;

    const unsigned sbase = (unsigned)__cvta_generic_to_shared(dynsmem);

    // Issue cp.async loads for chunk c into stage buf.
    auto load_chunk = [&](int c, int buf) {
        const unsigned* AhiS = (c < a1c0) ? A0hi : A1hi;
        const unsigned* AloS = (c < a1c0) ? A0lo : A1lo;
        const int akw = ((c < a1c0) ? c : (c - a1c0)) * 16;
        const unsigned bb = sbase + buf * BUF_B;
#pragma unroll
        for (int t = 0; t < 2; t++) {
            int idx = tid + t * 256;
            int row = idx >> 2, q = idx & 3;
            bool pred = (row0 + row) < nrows;
            int rc = pred ? (row0 + row) : (nrows - 1);
            size_t go = (size_t)rc * strAw + akw + q * 4;
            unsigned sb = bb + (row * STR + q * 4) * 4u;
            cpa16(sb, &AhiS[go], pred);
            cpa16(sb + PLANE_B, &AloS[go], pred);
        }
#pragma unroll
        for (int t = 0; t < 2; t++) {
            int idx = tid + t * 256;
            int o = idx >> 2, q = idx & 3;
            size_t go = (size_t)o * strBw + c * 16 + q * 4;
            unsigned sb = bb + 2 * PLANE_B + (o * STR + q * 4) * 4u;
            cpa16(sb, &Bhi_g[go], true);
            cpa16(sb + PLANE_B, &Blo_g[go], true);
        }
        cpa_commit();
    };

    float acc[4][4][4];
#pragma unroll
    for (int i = 0; i < 4; i++)
#pragma unroll
        for (int j = 0; j < 4; j++)
#pragma unroll
            for (int r = 0; r < 4; r++) acc[i][j][r] = 0.0f;

    load_chunk(0, 0);

    for (int c = 0; c < KCH; c++) {
        if (c + 1 < KCH) { load_chunk(c + 1, (c + 1) & 1); cpa_wait<1>(); }
        else             { cpa_wait<0>(); }
        __syncthreads();

        const unsigned bb = sbase + (c & 1) * BUF_B;
        const unsigned baseAhi = bb;
        const unsigned baseAlo = bb + PLANE_B;
        const unsigned baseBhi = bb + 2 * PLANE_B;
        const unsigned baseBlo = bb + 3 * PLANE_B;

#pragma unroll
        for (int s = 0; s < 2; s++) {
            unsigned ahi[4][4], alo[4][4];
#pragma unroll
            for (int tm = 0; tm < 4; tm++) {
                unsigned off = ((wm * 64 + tm * 16 + rowA) * STR + s * 8 + wordA) * 4u;
                ldmx4(ahi[tm], baseAhi + off);
                ldmx4(alo[tm], baseAlo + off);
            }
            unsigned bhi[4][2], blo[4][2];
#pragma unroll
            for (int tn = 0; tn < 4; tn++) {
                unsigned off = ((wn * 32 + tn * 8 + lr) * STR + s * 8 + wordB) * 4u;
                ldmx2(bhi[tn], baseBhi + off);
                ldmx2(blo[tn], baseBlo + off);
            }
#pragma unroll
            for (int tm = 0; tm < 4; tm++)
#pragma unroll
                for (int tn = 0; tn < 4; tn++) {
                    mma16816(acc[tm][tn], ahi[tm], bhi[tn]);
                    mma16816(acc[tm][tn], ahi[tm], blo[tn]);
                    mma16816(acc[tm][tn], alo[tm], bhi[tn]);
                }
        }
        __syncthreads();   // protect stage (c&1) before it is refilled at c+2
    }

#pragma unroll
    for (int tm = 0; tm < 4; tm++) {
#pragma unroll
        for (int tn = 0; tn < 4; tn++) {
            int col = wn * 32 + tn * 8 + (lane & 3) * 2;
            float b0 = bias[col], b1 = bias[col + 1];
            int r1 = row0 + wm * 64 + tm * 16 + (lane >> 2);
            if (r1 < nrows) {
                float2 v = make_float2(acc[tm][tn][0] + b0, acc[tm][tn][1] + b1);
                *reinterpret_cast<float2*>(&Cout[(size_t)r1 * strideC + col]) = v;
            }
            int r2 = r1 + 8;
            if (r2 < nrows) {
                float2 v = make_float2(acc[tm][tn][2] + b0, acc[tm][tn][3] + b1);
                *reinterpret_cast<float2*>(&Cout[(size_t)r2 * strideC + col]) = v;
            }
        }
    }
}

__global__ __launch_bounds__(256) void gemm_pool(const float* __restrict__ bp, int nrows)
{
    gemm_body<4>(g_feat_hi, g_feat_lo, g_feat_hi, g_feat_lo, 4, 64,
                 g_wp_hi, g_wp_lo, 64, bp, g_h, D, nrows);
}

__global__ __launch_bounds__(256) void gemm_out(
    const float* __restrict__ bn, float* __restrict__ out, int nrows)
{
    gemm_body<8>(g_feat_hi, g_feat_lo, g_neigh_hi, g_neigh_lo, 4, 64,
                 g_wn_hi, g_wn_lo, 128, bn, out, OUT, nrows);
}

// ---------------------------------------------------------------------------
// CSR build: histogram -> scan -> scatter
// ---------------------------------------------------------------------------
__global__ __launch_bounds__(256) void hist_kernel(const int* __restrict__ dst, int nedges)
{
    int e = blockIdx.x * 256 + threadIdx.x;
    if (e >= nedges) return;
    int d = dst[e];
    if ((unsigned)d < N_NODES) atomicAdd(&g_deg[d], 1);
}

__global__ __launch_bounds__(1024) void scan_kernel()
{
    __shared__ int totals[1024];
    const int CH = (N_NODES + 1023) / 1024;  // 49
    int t = threadIdx.x;
    int base = t * CH;

    int sum = 0;
#pragma unroll
    for (int i = 0; i < CH; i++) {
        int idx = base + i;
        if (idx < N_NODES) sum += g_deg[idx];
    }
    totals[t] = sum;
    __syncthreads();

    for (int s = 1; s < 1024; s <<= 1) {
        int v = (t >= s) ? totals[t - s] : 0;
        __syncthreads();
        totals[t] += v;
        __syncthreads();
    }

    int run = (t > 0) ? totals[t - 1] : 0;
    for (int i = 0; i < CH; i++) {
        int idx = base + i;
        if (idx < N_NODES) {
            g_off[idx] = run;
            g_cursor[idx] = run;
            run += g_deg[idx];
        }
    }
}

__global__ __launch_bounds__(256) void scatter_kernel(
    const float* __restrict__ weight,
    const int* __restrict__ src, const int* __restrict__ dst, int nedges)
{
    int e = blockIdx.x * 256 + threadIdx.x;
    if (e >= nedges) return;
    int s = src[e];
    int d = dst[e];
    if ((unsigned)s >= N_NODES || (unsigned)d >= N_NODES) return;
    int pos = atomicAdd(&g_cursor[d], 1);
    g_csr[pos] = make_int2(s, __float_as_int(weight[e]));
}

// ---------------------------------------------------------------------------
// Aggregate: one warp per node; shfl-broadcast CSR, 8-wide gather batches.
// Emits bf16 hi/lo planes directly.
// ---------------------------------------------------------------------------
__device__ __forceinline__ void fmax4(float4& acc, float4 v, float w) {
    acc.x = fmaxf(acc.x, v.x * w);
    acc.y = fmaxf(acc.y, v.y * w);
    acc.z = fmaxf(acc.z, v.z * w);
    acc.w = fmaxf(acc.w, v.w * w);
}

__global__ __launch_bounds__(256) void aggregate_kernel()
{
    int n = blockIdx.x * 8 + (threadIdx.x >> 5);
    if (n >= N_NODES) return;
    int lane = threadIdx.x & 31;

    int off = g_off[n];
    int deg = g_deg[n];

    float4 acc = make_float4(-CUDART_INF_F, -CUDART_INF_F, -CUDART_INF_F, -CUDART_INF_F);

    for (int base = 0; base < deg; base += 32) {
        int cnt = deg - base; if (cnt > 32) cnt = 32;
        int2 e = make_int2(0, 0);
        if (lane < cnt) e = g_csr[off + base + lane];

        for (int jb = 0; jb < cnt; jb += 8) {
            float4 v[8]; float w[8]; bool val[8];
#pragma unroll
            for (int u = 0; u < 8; u++) {
                int idx = jb + u;
                val[u] = idx < cnt;
                int idc = val[u] ? idx : 0;
                int s = __shfl_sync(0xffffffffu, e.x, idc);
                w[u] = __int_as_float(__shfl_sync(0xffffffffu, e.y, idc));
                v[u] = *reinterpret_cast<const float4*>(&g_h[(size_t)s * D + lane * 4]);
            }
#pragma unroll
            for (int u = 0; u < 8; u++)
                if (val[u]) fmax4(acc, v[u], w[u]);
        }
    }
    if (deg == 0) acc = make_float4(0.f, 0.f, 0.f, 0.f);

    unsigned h0, l0, h1, l1;
    split2(acc.x, acc.y, h0, l0);
    split2(acc.z, acc.w, h1, l1);
    size_t wi = (size_t)n * 64 + lane * 2;
    *reinterpret_cast<uint2*>(&g_neigh_hi[wi]) = make_uint2(h0, h1);
    *reinterpret_cast<uint2*>(&g_neigh_lo[wi]) = make_uint2(l0, l1);
}

// ---------------------------------------------------------------------------
extern "C" void kernel_launch(void* const* d_in, const int* in_sizes, int n_in,
                              void* d_out, int out_size)
{
    const float* feat   = (const float*)d_in[0];
    const float* weight = (const float*)d_in[1];
    const int*   src    = (const int*)d_in[2];
    const int*   dst    = (const int*)d_in[3];
    const float* Wp     = (const float*)d_in[4];
    const float* bp     = (const float*)d_in[5];
    const float* Wn     = (const float*)d_in[6];
    const float* bn     = (const float*)d_in[7];
    float* out = (float*)d_out;

    static cudaStream_t s1 = nullptr, s2 = nullptr;
    static cudaEvent_t evA = nullptr, ev1 = nullptr, ev2 = nullptr;
    if (!s1) {
        cudaStreamCreateWithFlags(&s1, cudaStreamNonBlocking);
        cudaStreamCreateWithFlags(&s2, cudaStreamNonBlocking);
        cudaEventCreateWithFlags(&evA, cudaEventDisableTiming);
        cudaEventCreateWithFlags(&ev1, cudaEventDisableTiming);
        cudaEventCreateWithFlags(&ev2, cudaEventDisableTiming);
        cudaFuncSetAttribute(gemm_pool, cudaFuncAttributeMaxDynamicSharedMemorySize, SMEM_TOT);
        cudaFuncSetAttribute(gemm_out,  cudaFuncAttributeMaxDynamicSharedMemorySize, SMEM_TOT);
    }

    void* deg_ptr = nullptr;
    cudaGetSymbolAddress(&deg_ptr, g_deg);
    unsigned *fh, *fl, *wph, *wpl, *wnh, *wnl;
    cudaGetSymbolAddress((void**)&fh,  g_feat_hi);
    cudaGetSymbolAddress((void**)&fl,  g_feat_lo);
    cudaGetSymbolAddress((void**)&wph, g_wp_hi);
    cudaGetSymbolAddress((void**)&wpl, g_wp_lo);
    cudaGetSymbolAddress((void**)&wnh, g_wn_hi);
    cudaGetSymbolAddress((void**)&wnl, g_wn_lo);

    // Fork: CSR chain on s1, split chain on s2, GEMMs on the capture stream.
    cudaEventRecord(evA, 0);

    cudaStreamWaitEvent(s1, evA, 0);
    cudaMemsetAsync(deg_ptr, 0, sizeof(int) * N_NODES, s1);
    int eb = (N_EDGES + 255) / 256;
    hist_kernel<<<eb, 256, 0, s1>>>(dst, N_EDGES);
    scan_kernel<<<1, 1024, 0, s1>>>();
    scatter_kernel<<<eb, 256, 0, s1>>>(weight, src, dst, N_EDGES);
    cudaEventRecord(ev1, s1);

    cudaStreamWaitEvent(s2, evA, 0);
    split_kernel<<<(N_NODES * 32 + 255) / 256, 256, 0, s2>>>(feat, fh, fl, N_NODES * 32);
    split_kernel<<<16, 256, 0, s2>>>(Wp, wph, wpl, 128 * 128 / 4);
    split_kernel<<<32, 256, 0, s2>>>(Wn, wnh, wnl, 128 * 256 / 4);
    cudaEventRecord(ev2, s2);

    cudaStreamWaitEvent(0, ev2, 0);
    int grid_rows = (N_NODES + 127) / 128;        // 391
    gemm_pool<<<grid_rows, 256, SMEM_TOT>>>(bp, N_NODES);

    cudaStreamWaitEvent(0, ev1, 0);
    aggregate_kernel<<<(N_NODES + 7) / 8, 256>>>();

    gemm_out<<<grid_rows, 256, SMEM_TOT>>>(bn, out, N_NODES);
}